// round 3
// baseline (speedup 1.0000x reference)
#include <cuda_runtime.h>
#include <cuda_bf16.h>
#include <math.h>

#define N_NODES 100000
#define N_EDGES 3200000

// ---------------- device scratch (allocation-free rule: __device__ globals) ---
__device__ int   g_is64;                // 1 if edge_index is int64, 0 if int32
__device__ int   g_cnt[N_NODES];        // in-degree (without self loop)
__device__ int   g_rowptr[N_NODES + 1]; // CSR row pointers (by dst)
__device__ int   g_cursor[N_NODES];     // fill cursors
__device__ int   g_srcs[N_EDGES];       // CSR column = src per dst bucket
__device__ float g_dinv[N_NODES];       // 1/sqrt(deg), deg includes self loop
__device__ float g_bufA[N_NODES * 64];  // tmp = (h @ W) * dinv[node]
__device__ float g_bufB[N_NODES * 64];  // h after aggregation + tanh

template <int TAG>
__device__ __forceinline__ float* buf_ptr() {
    return (TAG == 1) ? g_bufA : g_bufB;
}

// read edge entry 'idx' (0..2*N_EDGES-1) honoring detected dtype
__device__ __forceinline__ int edge_at(const void* ei, long long idx, int is64) {
    if (is64) return (int)((const long long*)ei)[idx];
    return ((const int*)ei)[idx];
}

// ---------------- dtype detection --------------------------------------------
// int64 data (values < 2^31, little-endian): every odd int32 word is 0.
// int32 data: odd words are random node ids -> almost surely nonzero somewhere.
__global__ void k_detect(const void* ei) {
    __shared__ int any_nz;
    if (threadIdx.x == 0) any_nz = 0;
    __syncthreads();
    const int* w = (const int*)ei;
    // sample 4096 odd words spread over the first 8192 int32 words
    for (int i = threadIdx.x; i < 4096; i += blockDim.x) {
        if (w[2 * i + 1] != 0) any_nz = 1;
    }
    __syncthreads();
    if (threadIdx.x == 0) g_is64 = any_nz ? 0 : 1;
}

// ---------------- CSR build --------------------------------------------------
__global__ void k_init_cnt() {
    int i = blockIdx.x * blockDim.x + threadIdx.x;
    if (i < N_NODES) g_cnt[i] = 0;
}

__global__ void k_count(const void* __restrict__ ei) {
    int e = blockIdx.x * blockDim.x + threadIdx.x;
    if (e < N_EDGES) {
        int is64 = g_is64;
        int s = edge_at(ei, e, is64);
        int d = edge_at(ei, (long long)N_EDGES + e, is64);
        if ((unsigned)s < N_NODES && (unsigned)d < N_NODES)
            atomicAdd(&g_cnt[d], 1);
    }
}

// single-block exclusive scan over g_cnt -> g_rowptr (N=100k, ~98 chunks)
__global__ void k_scan() {
    __shared__ int sh[1024];
    __shared__ int s_running;
    int tid = threadIdx.x;
    if (tid == 0) s_running = 0;
    __syncthreads();
    for (int base = 0; base < N_NODES; base += 1024) {
        int idx = base + tid;
        int v = (idx < N_NODES) ? g_cnt[idx] : 0;
        sh[tid] = v;
        __syncthreads();
        for (int off = 1; off < 1024; off <<= 1) {
            int t = (tid >= off) ? sh[tid - off] : 0;
            __syncthreads();
            sh[tid] += t;
            __syncthreads();
        }
        int incl = sh[tid];
        if (idx < N_NODES) g_rowptr[idx] = s_running + incl - v;  // exclusive
        __syncthreads();
        if (tid == 1023) s_running += sh[1023];
        __syncthreads();
    }
    if (tid == 0) g_rowptr[N_NODES] = s_running;
}

__global__ void k_finalize() {
    int i = blockIdx.x * blockDim.x + threadIdx.x;
    if (i < N_NODES) {
        g_dinv[i]   = rsqrtf((float)g_cnt[i] + 1.0f);  // +1 self loop
        g_cursor[i] = g_rowptr[i];
    }
}

__global__ void k_fill(const void* __restrict__ ei) {
    int e = blockIdx.x * blockDim.x + threadIdx.x;
    if (e < N_EDGES) {
        int is64 = g_is64;
        int s = edge_at(ei, e, is64);
        int d = edge_at(ei, (long long)N_EDGES + e, is64);
        if ((unsigned)s < N_NODES && (unsigned)d < N_NODES) {
            int p = atomicAdd(&g_cursor[d], 1);
            g_srcs[p] = s;
        }
    }
}

// ---------------- dense GEMM: DST[n,FOUT] = (SRC[n,FIN] @ W) * dinv[n] --------
template <int FIN, int FOUT, int SRC_TAG, int DST_TAG>
__global__ __launch_bounds__(256) void k_gemm_scale(
    const float* __restrict__ ext, const float* __restrict__ W)
{
    __shared__ float sW[FIN * FOUT];
    for (int i = threadIdx.x; i < FIN * FOUT; i += blockDim.x) sW[i] = W[i];
    __syncthreads();
    const float* h = (SRC_TAG == 0) ? ext : buf_ptr<SRC_TAG>();
    float* out = buf_ptr<DST_TAG>();
    int idx = blockIdx.x * blockDim.x + threadIdx.x;
    int node = idx / FOUT;
    int f    = idx % FOUT;
    if (node >= N_NODES) return;
    const float* hr = h + (size_t)node * FIN;
    float acc = 0.f;
#pragma unroll
    for (int k = 0; k < FIN; k++) acc += hr[k] * sW[k * FOUT + f];
    out[(size_t)node * FOUT + f] = acc * g_dinv[node];
}

// ---------------- aggregation: one warp per node -----------------------------
template <int FOUT, bool ACT, int SRC_TAG, int DST_TAG>
__global__ __launch_bounds__(256) void k_aggregate(const float* __restrict__ b)
{
    const float* tmp = buf_ptr<SRC_TAG>();
    float* out = buf_ptr<DST_TAG>();
    int warp = (blockIdx.x * blockDim.x + threadIdx.x) >> 5;
    int lane = threadIdx.x & 31;
    if (warp >= N_NODES) return;
    const int node = warp;
    constexpr int PER = (FOUT + 31) / 32;

    float acc[PER];
#pragma unroll
    for (int p = 0; p < PER; p++) {
        int f = lane + p * 32;
        acc[p] = (f < FOUT) ? tmp[(size_t)node * FOUT + f] : 0.f;  // self loop
    }

    int start = g_rowptr[node];
    int end   = g_rowptr[node + 1];
    for (int e0 = start; e0 < end; e0 += 32) {
        int idx = e0 + lane;
        int s   = (idx < end) ? g_srcs[idx] : 0;
        int m   = min(32, end - e0);
        for (int j = 0; j < m; j++) {
            int sj = __shfl_sync(0xffffffffu, s, j);
            const float* row = tmp + (size_t)sj * FOUT;
#pragma unroll
            for (int p = 0; p < PER; p++) {
                int f = lane + p * 32;
                if (f < FOUT) acc[p] += row[f];
            }
        }
    }

    float d = g_dinv[node];
#pragma unroll
    for (int p = 0; p < PER; p++) {
        int f = lane + p * 32;
        if (f < FOUT) {
            float v = d * acc[p] + b[f];
            out[(size_t)node * FOUT + f] = ACT ? tanhf(v) : v;
        }
    }
}

// ---------------- classifier + output packing --------------------------------
// d_out layout: [N*2 logits][N*8 hidden]; reads h from g_bufB
__global__ __launch_bounds__(256) void k_classify(
    const float* __restrict__ Wc, const float* __restrict__ bc,
    float* __restrict__ dout)
{
    const float* h = g_bufB;
    int i = blockIdx.x * blockDim.x + threadIdx.x;
    if (i >= N_NODES) return;
    float hv[8];
#pragma unroll
    for (int k = 0; k < 8; k++) hv[k] = h[(size_t)i * 8 + k];
#pragma unroll
    for (int c = 0; c < 2; c++) {
        float a = bc[c];
#pragma unroll
        for (int k = 0; k < 8; k++) a += hv[k] * Wc[k * 2 + c];
        dout[(size_t)i * 2 + c] = a;
    }
    float* dh = dout + (size_t)2 * N_NODES;
#pragma unroll
    for (int k = 0; k < 8; k++) dh[(size_t)i * 8 + k] = hv[k];
}

// ---------------- launcher ----------------------------------------------------
extern "C" void kernel_launch(void* const* d_in, const int* in_sizes, int n_in,
                              void* d_out, int out_size)
{
    const float* x  = (const float*)d_in[0];
    const void*  ei = d_in[1];
    const float* W1 = (const float*)d_in[2];
    const float* b1 = (const float*)d_in[3];
    const float* W2 = (const float*)d_in[4];
    const float* b2 = (const float*)d_in[5];
    const float* W3 = (const float*)d_in[6];
    const float* b3 = (const float*)d_in[7];
    const float* W4 = (const float*)d_in[8];
    const float* b4 = (const float*)d_in[9];
    const float* Wc = (const float*)d_in[10];
    const float* bc = (const float*)d_in[11];
    float* out = (float*)d_out;

    const int T = 256;
    const int eb = (N_EDGES + T - 1) / T;
    const int nb = (N_NODES + T - 1) / T;
    const int wb = (N_NODES * 32 + T - 1) / T;  // one warp per node

    // dtype detection + CSR build (by dst)
    k_detect<<<1, 256>>>(ei);
    k_init_cnt<<<nb, T>>>();
    k_count<<<eb, T>>>(ei);
    k_scan<<<1, 1024>>>();
    k_finalize<<<nb, T>>>();
    k_fill<<<eb, T>>>(ei);

    // layer 1: 34 -> 64   (x -> A -> B)
    k_gemm_scale<34, 64, 0, 1><<<(N_NODES * 64 + T - 1) / T, T>>>(x, W1);
    k_aggregate<64, true, 1, 2><<<wb, T>>>(b1);
    // layer 2: 64 -> 32   (B -> A -> B)
    k_gemm_scale<64, 32, 2, 1><<<(N_NODES * 32 + T - 1) / T, T>>>(nullptr, W2);
    k_aggregate<32, true, 1, 2><<<wb, T>>>(b2);
    // layer 3: 32 -> 16
    k_gemm_scale<32, 16, 2, 1><<<(N_NODES * 16 + T - 1) / T, T>>>(nullptr, W3);
    k_aggregate<16, true, 1, 2><<<wb, T>>>(b3);
    // layer 4: 16 -> 8
    k_gemm_scale<16, 8, 2, 1><<<(N_NODES * 8 + T - 1) / T, T>>>(nullptr, W4);
    k_aggregate<8, true, 1, 2><<<wb, T>>>(b4);

    // classifier + pack (logits then hidden), reads g_bufB
    k_classify<<<nb, T>>>(Wc, bc, out);
}

// round 4
// speedup vs baseline: 1.5405x; 1.5405x over previous
#include <cuda_runtime.h>
#include <cuda_bf16.h>
#include <math.h>

#define N_NODES 100000
#define N_EDGES 3200000
#define SCAN_B  512
#define SCAN_NBLK ((N_NODES + SCAN_B - 1) / SCAN_B)   // 196

// ---------------- device scratch ----------------------------------------------
__device__ int   g_is64;
__device__ int   g_cnt[N_NODES];
__device__ int   g_rowptr[N_NODES + 1];
__device__ int   g_cursor[N_NODES];
__device__ int   g_srcs[N_EDGES];
__device__ int   g_blksum[SCAN_NBLK];
__device__ int   g_blkoff[SCAN_NBLK];
__device__ float g_dinv[N_NODES];
__device__ float g_bufA[N_NODES * 64];
__device__ float g_bufB[N_NODES * 64];

template <int TAG>
__device__ __forceinline__ float* buf_ptr() {
    return (TAG == 1) ? g_bufA : g_bufB;
}

__device__ __forceinline__ int edge_at(const void* ei, long long idx, int is64) {
    if (is64) return (int)((const long long*)ei)[idx];
    return ((const int*)ei)[idx];
}

// ---------------- dtype detection ----------------------------------------------
__global__ void k_detect(const void* ei) {
    __shared__ int any_nz;
    if (threadIdx.x == 0) any_nz = 0;
    __syncthreads();
    const int* w = (const int*)ei;
    for (int i = threadIdx.x; i < 4096; i += blockDim.x)
        if (w[2 * i + 1] != 0) any_nz = 1;
    __syncthreads();
    if (threadIdx.x == 0) g_is64 = any_nz ? 0 : 1;
}

// ---------------- CSR build -----------------------------------------------------
__global__ void k_init_cnt() {
    int i = blockIdx.x * blockDim.x + threadIdx.x;
    if (i < N_NODES) g_cnt[i] = 0;
}

__global__ void k_count(const void* __restrict__ ei) {
    int e = blockIdx.x * blockDim.x + threadIdx.x;
    if (e < N_EDGES) {
        int is64 = g_is64;
        int s = edge_at(ei, e, is64);
        int d = edge_at(ei, (long long)N_EDGES + e, is64);
        if ((unsigned)s < N_NODES && (unsigned)d < N_NODES)
            atomicAdd(&g_cnt[d], 1);
    }
}

// --- hierarchical exclusive scan: local (196 blocks) -> block sums -> add ------
__global__ __launch_bounds__(SCAN_B) void k_scan_local() {
    __shared__ int wsum[SCAN_B / 32];
    int tid  = threadIdx.x;
    int lane = tid & 31;
    int wid  = tid >> 5;
    int idx  = blockIdx.x * SCAN_B + tid;
    int v = (idx < N_NODES) ? g_cnt[idx] : 0;

    // warp inclusive scan
    int incl = v;
#pragma unroll
    for (int off = 1; off < 32; off <<= 1) {
        int t = __shfl_up_sync(0xffffffffu, incl, off);
        if (lane >= off) incl += t;
    }
    if (lane == 31) wsum[wid] = incl;
    __syncthreads();
    if (wid == 0) {
        int ws = (lane < SCAN_B / 32) ? wsum[lane] : 0;
#pragma unroll
        for (int off = 1; off < SCAN_B / 32; off <<= 1) {
            int t = __shfl_up_sync(0xffffffffu, ws, off);
            if (lane >= off) ws += t;
        }
        if (lane < SCAN_B / 32) wsum[lane] = ws;  // inclusive warp-sum scan
    }
    __syncthreads();
    int base = (wid > 0) ? wsum[wid - 1] : 0;
    int excl = base + incl - v;
    if (idx < N_NODES) g_rowptr[idx] = excl;  // local exclusive, offset added later
    if (tid == SCAN_B - 1) g_blksum[blockIdx.x] = base + incl;
}

__global__ __launch_bounds__(256) void k_scan_blk() {
    __shared__ int sh[256];
    int tid = threadIdx.x;
    int v = (tid < SCAN_NBLK) ? g_blksum[tid] : 0;
    sh[tid] = v;
    __syncthreads();
#pragma unroll
    for (int off = 1; off < 256; off <<= 1) {
        int t = (tid >= off) ? sh[tid - off] : 0;
        __syncthreads();
        sh[tid] += t;
        __syncthreads();
    }
    if (tid < SCAN_NBLK) g_blkoff[tid] = sh[tid] - v;  // exclusive
}

// add block offsets + finalize (dinv, cursor, rowptr[N])
__global__ __launch_bounds__(256) void k_scan_add() {
    int i = blockIdx.x * blockDim.x + threadIdx.x;
    if (i < N_NODES) {
        int rp = g_rowptr[i] + g_blkoff[i / SCAN_B];
        g_rowptr[i] = rp;
        g_cursor[i] = rp;
        g_dinv[i]   = rsqrtf((float)g_cnt[i] + 1.0f);  // +1 self loop
    }
    if (i == 0) g_rowptr[N_NODES] =
        g_blkoff[SCAN_NBLK - 1] + g_blksum[SCAN_NBLK - 1];
}

__global__ void k_fill(const void* __restrict__ ei) {
    int e = blockIdx.x * blockDim.x + threadIdx.x;
    if (e < N_EDGES) {
        int is64 = g_is64;
        int s = edge_at(ei, e, is64);
        int d = edge_at(ei, (long long)N_EDGES + e, is64);
        if ((unsigned)s < N_NODES && (unsigned)d < N_NODES) {
            int p = atomicAdd(&g_cursor[d], 1);
            g_srcs[p] = s;
        }
    }
}

// ---------------- dense GEMM: DST[n,FOUT] = (SRC[n,FIN] @ W) * dinv[n] ----------
template <int FIN, int FOUT, int SRC_TAG, int DST_TAG>
__global__ __launch_bounds__(256) void k_gemm_scale(
    const float* __restrict__ ext, const float* __restrict__ W)
{
    __shared__ float sW[FIN * FOUT];
    for (int i = threadIdx.x; i < FIN * FOUT; i += blockDim.x) sW[i] = W[i];
    __syncthreads();
    const float* h = (SRC_TAG == 0) ? ext : buf_ptr<SRC_TAG>();
    float* out = buf_ptr<DST_TAG>();
    int idx = blockIdx.x * blockDim.x + threadIdx.x;
    int node = idx / FOUT;
    int f    = idx % FOUT;
    if (node >= N_NODES) return;
    const float* hr = h + (size_t)node * FIN;
    float acc = 0.f;
#pragma unroll
    for (int k = 0; k < FIN; k++) acc += hr[k] * sW[k * FOUT + f];
    out[(size_t)node * FOUT + f] = acc * g_dinv[node];
}

// ---------------- aggregation, FOUT=64: warp/node, float2 gathers ---------------
template <int SRC_TAG, int DST_TAG>
__global__ __launch_bounds__(256) void k_aggregate64(const float* __restrict__ b)
{
    const float2* tmp2 = (const float2*)buf_ptr<SRC_TAG>();
    float2* out2 = (float2*)buf_ptr<DST_TAG>();
    int warp = (blockIdx.x * blockDim.x + threadIdx.x) >> 5;
    int lane = threadIdx.x & 31;
    if (warp >= N_NODES) return;
    const int node = warp;

    float2 self = tmp2[(size_t)node * 32 + lane];
    float ax = self.x, ay = self.y;

    int start = g_rowptr[node];
    int end   = g_rowptr[node + 1];
    for (int e0 = start; e0 < end; e0 += 32) {
        int idx = e0 + lane;
        int s   = (idx < end) ? g_srcs[idx] : 0;
        int m   = min(32, end - e0);
        for (int j = 0; j < m; j++) {
            int sj = __shfl_sync(0xffffffffu, s, j);
            float2 r = tmp2[(size_t)sj * 32 + lane];
            ax += r.x; ay += r.y;
        }
    }
    float d = g_dinv[node];
    float2 bv = ((const float2*)b)[lane];
    float2 o;
    o.x = tanhf(d * ax + bv.x);
    o.y = tanhf(d * ay + bv.y);
    out2[(size_t)node * 32 + lane] = o;
}

// ---------------- aggregation, FOUT<=32: SPLIT subgroups per warp ---------------
template <int FOUT, bool ACT, int SRC_TAG, int DST_TAG>
__global__ __launch_bounds__(256) void k_aggregate_small(const float* __restrict__ b)
{
    constexpr int SPLIT = 32 / FOUT;
    const float* tmp = buf_ptr<SRC_TAG>();
    float* out = buf_ptr<DST_TAG>();
    int warp = (blockIdx.x * blockDim.x + threadIdx.x) >> 5;
    int lane = threadIdx.x & 31;
    if (warp >= N_NODES) return;
    const int node = warp;
    int sub = lane / FOUT;
    int f   = lane % FOUT;

    float acc0 = (sub == 0) ? tmp[(size_t)node * FOUT + f] : 0.f;  // self loop
    float acc1 = 0.f;

    int start = g_rowptr[node];
    int end   = g_rowptr[node + 1];
    int e = start + sub;
    for (; e + SPLIT < end; e += 2 * SPLIT) {
        int s0 = g_srcs[e];
        int s1 = g_srcs[e + SPLIT];
        acc0 += tmp[(size_t)s0 * FOUT + f];
        acc1 += tmp[(size_t)s1 * FOUT + f];
    }
    if (e < end) acc0 += tmp[(size_t)g_srcs[e] * FOUT + f];
    acc0 += acc1;

    // combine subgroups
#pragma unroll
    for (int off = FOUT; off < 32; off <<= 1)
        acc0 += __shfl_xor_sync(0xffffffffu, acc0, off);

    if (sub == 0) {
        float v = g_dinv[node] * acc0 + b[f];
        out[(size_t)node * FOUT + f] = ACT ? tanhf(v) : v;
    }
}

// ---------------- classifier + output packing -----------------------------------
__global__ __launch_bounds__(256) void k_classify(
    const float* __restrict__ Wc, const float* __restrict__ bc,
    float* __restrict__ dout)
{
    const float* h = g_bufB;
    int i = blockIdx.x * blockDim.x + threadIdx.x;
    if (i >= N_NODES) return;
    float hv[8];
#pragma unroll
    for (int k = 0; k < 8; k++) hv[k] = h[(size_t)i * 8 + k];
#pragma unroll
    for (int c = 0; c < 2; c++) {
        float a = bc[c];
#pragma unroll
        for (int k = 0; k < 8; k++) a += hv[k] * Wc[k * 2 + c];
        dout[(size_t)i * 2 + c] = a;
    }
    float* dh = dout + (size_t)2 * N_NODES;
#pragma unroll
    for (int k = 0; k < 8; k++) dh[(size_t)i * 8 + k] = hv[k];
}

// ---------------- launcher --------------------------------------------------------
extern "C" void kernel_launch(void* const* d_in, const int* in_sizes, int n_in,
                              void* d_out, int out_size)
{
    const float* x  = (const float*)d_in[0];
    const void*  ei = d_in[1];
    const float* W1 = (const float*)d_in[2];
    const float* b1 = (const float*)d_in[3];
    const float* W2 = (const float*)d_in[4];
    const float* b2 = (const float*)d_in[5];
    const float* W3 = (const float*)d_in[6];
    const float* b3 = (const float*)d_in[7];
    const float* W4 = (const float*)d_in[8];
    const float* b4 = (const float*)d_in[9];
    const float* Wc = (const float*)d_in[10];
    const float* bc = (const float*)d_in[11];
    float* out = (float*)d_out;

    const int T = 256;
    const int eb = (N_EDGES + T - 1) / T;
    const int nb = (N_NODES + T - 1) / T;
    const int wb = (N_NODES * 32 + T - 1) / T;  // one warp per node

    // dtype detection + CSR build (by dst)
    k_detect<<<1, 256>>>(ei);
    k_init_cnt<<<nb, T>>>();
    k_count<<<eb, T>>>(ei);
    k_scan_local<<<SCAN_NBLK, SCAN_B>>>();
    k_scan_blk<<<1, 256>>>();
    k_scan_add<<<nb, T>>>();
    k_fill<<<eb, T>>>(ei);

    // layer 1: 34 -> 64   (x -> A -> B)
    k_gemm_scale<34, 64, 0, 1><<<(N_NODES * 64 + T - 1) / T, T>>>(x, W1);
    k_aggregate64<1, 2><<<wb, T>>>(b1);
    // layer 2: 64 -> 32   (B -> A -> B)
    k_gemm_scale<64, 32, 2, 1><<<(N_NODES * 32 + T - 1) / T, T>>>(nullptr, W2);
    k_aggregate_small<32, true, 1, 2><<<wb, T>>>(b2);
    // layer 3: 32 -> 16
    k_gemm_scale<32, 16, 2, 1><<<(N_NODES * 16 + T - 1) / T, T>>>(nullptr, W3);
    k_aggregate_small<16, true, 1, 2><<<wb, T>>>(b3);
    // layer 4: 16 -> 8
    k_gemm_scale<16, 8, 2, 1><<<(N_NODES * 8 + T - 1) / T, T>>>(nullptr, W4);
    k_aggregate_small<8, true, 1, 2><<<wb, T>>>(b4);

    // classifier + pack (logits then hidden), reads g_bufB
    k_classify<<<nb, T>>>(Wc, bc, out);
}